// round 14
// baseline (speedup 1.0000x reference)
#include <cuda_runtime.h>
#include <cuda_bf16.h>
#include <cstdint>
#include <cstddef>

#define B_ 8
#define S_ 4096
#define D_ 512
#define C_ 16
#define NCH_ (S_ / C_)
#define M_TOT (B_ * S_)

static __device__ __constant__ float kEPS = 1e-6f;

__device__ float g_q[(size_t)B_ * S_ * D_];
__device__ float g_k[(size_t)B_ * S_ * D_];
__device__ float g_v[(size_t)B_ * S_ * D_];
__device__ float g_a[(size_t)B_ * S_ * D_];
__device__ __nv_bfloat16 g_xhi[(size_t)M_TOT * D_];
__device__ __nv_bfloat16 g_xlo[(size_t)M_TOT * D_];
__device__ __nv_bfloat16 g_whi[4 * D_ * D_];
__device__ __nv_bfloat16 g_wlo[4 * D_ * D_];

typedef uint32_t u32;

__device__ __forceinline__ uint32_t smem_u32(const void* p) {
    uint32_t a;
    asm("{ .reg .u64 t; cvta.to.shared.u64 t, %1; cvt.u32.u64 %0, t; }"
        : "=r"(a) : "l"(p));
    return a;
}
__device__ __forceinline__ void ldsm4(u32* r, u32 addr) {
    asm volatile("ldmatrix.sync.aligned.m8n8.x4.shared.b16 {%0,%1,%2,%3}, [%4];"
                 : "=r"(r[0]), "=r"(r[1]), "=r"(r[2]), "=r"(r[3]) : "r"(addr));
}
__device__ __forceinline__ void ldsm4t(u32* r, u32 addr) {
    asm volatile("ldmatrix.sync.aligned.m8n8.x4.trans.shared.b16 {%0,%1,%2,%3}, [%4];"
                 : "=r"(r[0]), "=r"(r[1]), "=r"(r[2]), "=r"(r[3]) : "r"(addr));
}
__device__ __forceinline__ u32 movmt(u32 a) {
    u32 d;
    asm volatile("movmatrix.sync.aligned.m8n8.trans.b16 %0, %1;" : "=r"(d) : "r"(a));
    return d;
}
__device__ __forceinline__ u32 bfpack(float lo, float hi) {
    u32 d;
    asm("cvt.rn.bf16x2.f32 %0, %1, %2;" : "=r"(d) : "f"(hi), "f"(lo));
    return d;
}
__device__ __forceinline__ float bfres(float x) {
    return x - __bfloat162float(__float2bfloat16(x));
}
__device__ __forceinline__ void mma16816(float* c, const u32* a, u32 b0, u32 b1) {
    asm volatile(
        "mma.sync.aligned.m16n8k16.row.col.f32.bf16.bf16.f32 "
        "{%0,%1,%2,%3}, {%4,%5,%6,%7}, {%8,%9}, {%0,%1,%2,%3};"
        : "+f"(c[0]), "+f"(c[1]), "+f"(c[2]), "+f"(c[3])
        : "r"(a[0]), "r"(a[1]), "r"(a[2]), "r"(a[3]), "r"(b0), "r"(b1));
}
__device__ __forceinline__ void cp16(u32 saddr, const void* g) {
    asm volatile("cp.async.cg.shared.global [%0], [%1], 16;" :: "r"(saddr), "l"(g));
}
__device__ __forceinline__ float act_apply(float x, int act) {
    if (act == 1) return fmaxf(x, 0.0f);
    if (act == 2) return 1.0f / (1.0f + __expf(-x));
    return x;
}

// -------------------- converts --------------------
__global__ void __launch_bounds__(256) convert_split_kernel(
    const float* __restrict__ src, __nv_bfloat16* __restrict__ hi,
    __nv_bfloat16* __restrict__ lo, int n2)
{
    const int idx = blockIdx.x * blockDim.x + threadIdx.x;
    const int stride = gridDim.x * blockDim.x;
    const float2* s2 = (const float2*)src;
    __nv_bfloat162* h2 = (__nv_bfloat162*)hi;
    __nv_bfloat162* l2 = (__nv_bfloat162*)lo;
    for (int i = idx; i < n2; i += stride) {
        const float2 x = s2[i];
        const __nv_bfloat16 h0 = __float2bfloat16(x.x);
        const __nv_bfloat16 h1 = __float2bfloat16(x.y);
        __nv_bfloat162 hh; hh.x = h0; hh.y = h1;
        __nv_bfloat162 ll;
        ll.x = __float2bfloat16(x.x - __bfloat162float(h0));
        ll.y = __float2bfloat16(x.y - __bfloat162float(h1));
        h2[i] = hh; l2[i] = ll;
    }
}

__global__ void __launch_bounds__(256) convert_w_kernel(
    const float* __restrict__ w0, const float* __restrict__ w1,
    const float* __restrict__ w2, const float* __restrict__ w3)
{
    const int wsel = blockIdx.y;
    const float* src = (wsel == 0) ? w0 : (wsel == 1) ? w1 : (wsel == 2) ? w2 : w3;
    __nv_bfloat162* h2 = (__nv_bfloat162*)(g_whi + (size_t)wsel * D_ * D_);
    __nv_bfloat162* l2 = (__nv_bfloat162*)(g_wlo + (size_t)wsel * D_ * D_);
    const float2* s2 = (const float2*)src;
    const int n2 = (D_ * D_) / 2;
    const int idx = blockIdx.x * blockDim.x + threadIdx.x;
    const int stride = gridDim.x * blockDim.x;
    for (int i = idx; i < n2; i += stride) {
        const float2 x = s2[i];
        const __nv_bfloat16 h0 = __float2bfloat16(x.x);
        const __nv_bfloat16 h1 = __float2bfloat16(x.y);
        __nv_bfloat162 hh; hh.x = h0; hh.y = h1;
        __nv_bfloat162 ll;
        ll.x = __float2bfloat16(x.x - __bfloat162float(h0));
        ll.y = __float2bfloat16(x.y - __bfloat162float(h1));
        h2[i] = hh; l2[i] = ll;
    }
}

// -------------------- projection GEMM (proven) --------------------
#define GK 32
#define NKCH (D_ / GK)
#define ROWB 80
#define TILEB (128 * ROWB)
#define ABUF_HI 0
#define ABUF_LO TILEB
#define BBUF_HI (2 * TILEB)
#define BBUF_LO (3 * TILEB)
#define BUFB (4 * TILEB)
#define GEMM_SMEM (2 * BUFB)

__global__ void __launch_bounds__(256, 1) proj_mma_kernel(
    const float* __restrict__ bq, const float* __restrict__ bk,
    const float* __restrict__ bv, const float* __restrict__ ba)
{
    extern __shared__ __align__(16) char smem[];
    const u32 sbase = smem_u32(smem);
    const int pz = blockIdx.z;
    const float* bias; float* out; int act;
    if (pz == 0)      { bias = bq; out = g_q; act = 1; }
    else if (pz == 1) { bias = bk; out = g_k; act = 1; }
    else if (pz == 2) { bias = bv; out = g_v; act = 0; }
    else              { bias = ba; out = g_a; act = 2; }

    const int tid = threadIdx.x, w = tid >> 5, l = tid & 31;
    const int wm = w >> 2, wn = w & 3;
    const int mBase = blockIdx.y * 128, nBase = blockIdx.x * 128;
    const __nv_bfloat16* Whi = g_whi + (size_t)pz * D_ * D_;
    const __nv_bfloat16* Wlo = g_wlo + (size_t)pz * D_ * D_;
    const int r0s = tid >> 2, s0s = tid & 3;
    const int r1s = (tid + 256) >> 2, s1s = tid & 3;

    auto load_chunk = [&](int buf, int kc) {
        const u32 sb = sbase + buf * BUFB;
        const int k0 = kc * GK;
        {
            const size_t ga = (size_t)(mBase + r0s) * D_ + k0 + s0s * 8;
            const size_t gb = (size_t)(nBase + r0s) * D_ + k0 + s0s * 8;
            const u32 so = r0s * ROWB + s0s * 16;
            cp16(sb + ABUF_HI + so, g_xhi + ga);
            cp16(sb + ABUF_LO + so, g_xlo + ga);
            cp16(sb + BBUF_HI + so, Whi + gb);
            cp16(sb + BBUF_LO + so, Wlo + gb);
        }
        {
            const size_t ga = (size_t)(mBase + r1s) * D_ + k0 + s1s * 8;
            const size_t gb = (size_t)(nBase + r1s) * D_ + k0 + s1s * 8;
            const u32 so = r1s * ROWB + s1s * 16;
            cp16(sb + ABUF_HI + so, g_xhi + ga);
            cp16(sb + ABUF_LO + so, g_xlo + ga);
            cp16(sb + BBUF_HI + so, Whi + gb);
            cp16(sb + BBUF_LO + so, Wlo + gb);
        }
        asm volatile("cp.async.commit_group;");
    };

    float acc[4][4][4];
#pragma unroll
    for (int i = 0; i < 4; ++i)
#pragma unroll
        for (int j = 0; j < 4; ++j)
#pragma unroll
            for (int e = 0; e < 4; ++e) acc[i][j][e] = 0.0f;

    const int lrow = l & 15, lcol16 = (l >> 4) & 1;
    load_chunk(0, 0);

#pragma unroll 1
    for (int kc = 0; kc < NKCH; ++kc) {
        const int buf = kc & 1;
        if (kc + 1 < NKCH) {
            load_chunk(buf ^ 1, kc + 1);
            asm volatile("cp.async.wait_group 1;");
        } else {
            asm volatile("cp.async.wait_group 0;");
        }
        __syncthreads();
        const u32 sb = sbase + buf * BUFB;
#pragma unroll
        for (int kh = 0; kh < 2; ++kh) {
            const u32 coff = kh * 32 + lcol16 * 16;
            u32 ah[4][4], al[4][4];
#pragma unroll
            for (int mt = 0; mt < 4; ++mt) {
                const u32 ra = (wm * 64 + mt * 16 + lrow) * ROWB + coff;
                ldsm4(ah[mt], sb + ABUF_HI + ra);
                ldsm4(al[mt], sb + ABUF_LO + ra);
            }
            u32 bh[2][4], bl[2][4];
#pragma unroll
            for (int bt = 0; bt < 2; ++bt) {
                const u32 rb = (wn * 32 + bt * 16 + lrow) * ROWB + coff;
                ldsm4(bh[bt], sb + BBUF_HI + rb);
                ldsm4(bl[bt], sb + BBUF_LO + rb);
            }
#pragma unroll
            for (int mt = 0; mt < 4; ++mt)
#pragma unroll
                for (int nt = 0; nt < 4; ++nt) {
                    const int bt = nt >> 1, hf = nt & 1;
                    mma16816(acc[mt][nt], ah[mt], bh[bt][hf], bh[bt][hf + 2]);
                    mma16816(acc[mt][nt], ah[mt], bl[bt][hf], bl[bt][hf + 2]);
                    mma16816(acc[mt][nt], al[mt], bh[bt][hf], bh[bt][hf + 2]);
                }
        }
        __syncthreads();
    }

#pragma unroll
    for (int nt = 0; nt < 4; ++nt) {
        const int col = nBase + wn * 32 + nt * 8 + 2 * (l & 3);
        const float2 b2 = *(const float2*)(bias + col);
#pragma unroll
        for (int mt = 0; mt < 4; ++mt) {
            const int row = mBase + wm * 64 + mt * 16 + (l >> 2);
            float2 r0, r1;
            r0.x = act_apply(acc[mt][nt][0] + b2.x, act);
            r0.y = act_apply(acc[mt][nt][1] + b2.y, act);
            r1.x = act_apply(acc[mt][nt][2] + b2.x, act);
            r1.y = act_apply(acc[mt][nt][3] + b2.y, act);
            *(float2*)(out + (size_t)row * D_ + col) = r0;
            *(float2*)(out + (size_t)(row + 8) * D_ + col) = r1;
        }
    }
}

// -------------------- pipelined tensor-core chunked scan --------------------
// Double-buffered staged operands; stage(ch+1) overlaps mma(ch); 3 barriers.
#define ST_I 1040
#define SB_QH 0
#define SB_QL 16640
#define SB_KH 33280
#define SB_KL 49920
#define SB_VH 66560
#define SB_VL 68096
#define SB_AC 69632
#define SBUFSZ 71680
#define ODNR (2 * SBUFSZ)            // [256][17] f32: pair-reduced den partials
#define ODP  (ODNR + 17408)          // [2][16*17] f32: den group sums (dbl-buf)
#define OPP  (ODP + 4352)            // [256][17] f32: P partials
#define OPA  (OPP + 17408)           // [16][528] f32: Q~S0 partials
#define ONA  (OPA + 33792)           // [528] f32: reduced numerator-A
#define OPH  (ONA + 2112)            // 16*48: P bf16 hi
#define OPL  (OPH + 768)             // 16*48: P bf16 lo
#define SCAN_SMEM (OPL + 768)        // 219,936 B total (wait: 2176*2=4352)

__global__ void __launch_bounds__(512, 1) scan_mma_kernel(float* __restrict__ y)
{
    extern __shared__ __align__(16) char sm[];
    const u32 sb = smem_u32(sm);
    float* fDNr = (float*)(sm + ODNR);
    float* fDP  = (float*)(sm + ODP);
    float* fPP  = (float*)(sm + OPP);
    float* fPA  = (float*)(sm + OPA);
    float* fNA  = (float*)(sm + ONA);

    const int b = blockIdx.y, jbase = blockIdx.x * 32;
    const int tid = threadIdx.x, w = tid >> 5, l = tid & 31;
    const float* gq = g_q + (size_t)b * S_ * D_;
    const float* gk = g_k + (size_t)b * S_ * D_;
    const float* gv = g_v + (size_t)b * S_ * D_;
    const float* ga = g_a + (size_t)b * S_ * D_;
    float* gy = y + (size_t)b * S_ * D_;

    float SA[2][4][4];
#pragma unroll
    for (int mt = 0; mt < 2; ++mt)
#pragma unroll
        for (int nt = 0; nt < 4; ++nt)
#pragma unroll
            for (int e = 0; e < 4; ++e) SA[mt][nt][e] = 0.0f;
    float zreg = 0.0f;

    const int l7 = l & 7;
    const u32 aTI  = (u32)((l7 + 8 * ((l >> 3) & 1)) * ST_I + 16 * (l >> 4));
    const u32 aTIt = (u32)((l7 + 8 * ((l >> 4) & 1)) * ST_I + 16 * ((l >> 3) & 1));
    const u32 a48  = (u32)((l7 + 8 * ((l >> 3) & 1)) * 48 + 16 * (l >> 4));

    // stage chunk `chk` into staged buffer chk&1 (incl. pair-reduced den)
    auto stage = [&](int chk) {
        char* smb = sm + (chk & 1) * SBUFSZ;
        const int t0 = chk * C_;
        const int i_ = tid;
        float av[16], A[16], iA[16], qv[16], kv[16];
#pragma unroll
        for (int t = 0; t < 16; ++t) av[t] = ga[(size_t)(t0 + t) * D_ + i_];
#pragma unroll
        for (int t = 0; t < 16; ++t) qv[t] = gq[(size_t)(t0 + t) * D_ + i_];
#pragma unroll
        for (int t = 0; t < 16; ++t) kv[t] = gk[(size_t)(t0 + t) * D_ + i_];
        A[0] = av[0];
#pragma unroll
        for (int t = 1; t < 16; ++t) A[t] = A[t - 1] * av[t];
        iA[15] = __frcp_rn(A[15]);
#pragma unroll
        for (int t = 15; t >= 1; --t) iA[t - 1] = iA[t] * av[t];
        float zu = zreg;
#pragma unroll
        for (int t = 0; t < 16; ++t) {
            const float qt = qv[t] * A[t];
            const float kt = kv[t] * iA[t];
            zu += kt;
            float dp = qt * zu;
            dp += __shfl_xor_sync(0xffffffffu, dp, 16);
            if (l < 16) fDNr[(w * 16 + l) * 17 + t] = dp;
            const __nv_bfloat16 qh = __float2bfloat16(qt);
            const __nv_bfloat16 kh = __float2bfloat16(kt);
            *(__nv_bfloat16*)(smb + SB_QH + t * ST_I + i_ * 2) = qh;
            *(__nv_bfloat16*)(smb + SB_QL + t * ST_I + i_ * 2) =
                __float2bfloat16(qt - __bfloat162float(qh));
            *(__nv_bfloat16*)(smb + SB_KH + t * ST_I + i_ * 2) = kh;
            *(__nv_bfloat16*)(smb + SB_KL + t * ST_I + i_ * 2) =
                __float2bfloat16(kt - __bfloat162float(kh));
        }
        zreg = A[15] * zu;
        ((float*)(smb + SB_AC))[i_] = A[15];
        // V staging [j][t]
        const int tv = tid >> 5, j = l;
        const float vv = gv[(size_t)(t0 + tv) * D_ + jbase + j];
        const __nv_bfloat16 vh = __float2bfloat16(vv);
        *(__nv_bfloat16*)(smb + SB_VH + j * 48 + tv * 2) = vh;
        *(__nv_bfloat16*)(smb + SB_VL + j * 48 + tv * 2) =
            __float2bfloat16(vv - __bfloat162float(vh));
    };

    // ---------------- prologue: stage chunk 0, prime DP[0] ----------------
    stage(0);
    __syncthreads();
    if (tid < 256) {
        const int t = tid & 15, g = tid >> 4;
        float s = 0.0f;
#pragma unroll
        for (int m = 0; m < 16; ++m) s += fDNr[(g * 16 + m) * 17 + t];
        fDP[t * 17 + g] = s;
    }
    __syncthreads();

#pragma unroll 1
    for (int ch = 0; ch < NCH_; ++ch) {
        const int buf = ch & 1;
        const u32 sbuf = sb + buf * SBUFSZ;
        char* smbuf = sm + buf * SBUFSZ;
        const int t0 = ch * C_;

        // ---- stage next chunk (no barrier before mma: buffers disjoint) ----
        if (ch + 1 < NCH_) stage(ch + 1);

        // ---- mma phase on staged[buf] ----
        u32 qhf[2][4], qlf[2][4];
        {
            u32 khf[2][4], klf[2][4];
#pragma unroll
            for (int ks = 0; ks < 2; ++ks) {
                const u32 io = (u32)(w * 32 + ks * 16) * 2;
                ldsm4(qhf[ks], sbuf + SB_QH + aTI + io);
                ldsm4(qlf[ks], sbuf + SB_QL + aTI + io);
                ldsm4(khf[ks], sbuf + SB_KH + aTI + io);
                ldsm4(klf[ks], sbuf + SB_KL + aTI + io);
            }
            float p0[4] = {0, 0, 0, 0}, p1[4] = {0, 0, 0, 0};
#pragma unroll
            for (int ks = 0; ks < 2; ++ks) {
                mma16816(p0, qhf[ks], khf[ks][0], khf[ks][2]);
                mma16816(p0, qlf[ks], khf[ks][0], khf[ks][2]);
                mma16816(p0, qhf[ks], klf[ks][0], klf[ks][2]);
                mma16816(p1, qhf[ks], khf[ks][1], khf[ks][3]);
                mma16816(p1, qlf[ks], khf[ks][1], khf[ks][3]);
                mma16816(p1, qhf[ks], klf[ks][1], klf[ks][3]);
            }
#pragma unroll
            for (int e = 0; e < 4; ++e) {
                const int tr = (l >> 2) + (e >> 1) * 8;
                const int tc = 2 * (l & 3) + (e & 1);
                fPP[(tr * 16 + tc) * 17 + w] = p0[e];
                fPP[(tr * 16 + tc + 8) * 17 + w] = p1[e];
            }
        }
        {
            float qs[4][4];
#pragma unroll
            for (int nt = 0; nt < 4; ++nt)
#pragma unroll
                for (int e = 0; e < 4; ++e) qs[nt][e] = 0.0f;
#pragma unroll
            for (int mt = 0; mt < 2; ++mt)
#pragma unroll
                for (int nt = 0; nt < 4; ++nt) {
                    const float c0 = SA[mt][nt][0], c1 = SA[mt][nt][1];
                    const float c2 = SA[mt][nt][2], c3 = SA[mt][nt][3];
                    const u32 b0h = movmt(bfpack(c0, c1));
                    const u32 b1h = movmt(bfpack(c2, c3));
                    const u32 b0l = movmt(bfpack(bfres(c0), bfres(c1)));
                    const u32 b1l = movmt(bfpack(bfres(c2), bfres(c3)));
                    mma16816(qs[nt], qhf[mt], b0h, b1h);
                    mma16816(qs[nt], qlf[mt], b0h, b1h);
                    mma16816(qs[nt], qhf[mt], b0l, b1l);
                }
#pragma unroll
            for (int nt = 0; nt < 4; ++nt)
#pragma unroll
                for (int e = 0; e < 4; ++e) {
                    const int tr = (l >> 2) + (e >> 1) * 8;
                    const int j = nt * 8 + 2 * (l & 3) + (e & 1);
                    fPA[w * 528 + tr * 33 + j] = qs[nt][e];
                }
        }
        {
            u32 ah[2][4], al[2][4], vh[2][4], vl[2][4];
#pragma unroll
            for (int mt = 0; mt < 2; ++mt) {
                const u32 io = (u32)(w * 32 + mt * 16) * 2;
                ldsm4t(ah[mt], sbuf + SB_KH + aTIt + io);
                ldsm4t(al[mt], sbuf + SB_KL + aTIt + io);
            }
#pragma unroll
            for (int jg = 0; jg < 2; ++jg) {
                ldsm4(vh[jg], sbuf + SB_VH + a48 + jg * 768);
                ldsm4(vl[jg], sbuf + SB_VL + a48 + jg * 768);
            }
#pragma unroll
            for (int mt = 0; mt < 2; ++mt)
#pragma unroll
                for (int nt = 0; nt < 4; ++nt) {
                    const int jg = nt >> 1, hf = nt & 1;
                    mma16816(SA[mt][nt], ah[mt], vh[jg][hf], vh[jg][hf + 2]);
                    mma16816(SA[mt][nt], al[mt], vh[jg][hf], vh[jg][hf + 2]);
                    mma16816(SA[mt][nt], ah[mt], vl[jg][hf], vl[jg][hf + 2]);
                }
            const float* fACb = (const float*)(smbuf + SB_AC);
#pragma unroll
            for (int mt = 0; mt < 2; ++mt) {
                const float s0 = fACb[w * 32 + mt * 16 + (l >> 2)];
                const float s8 = fACb[w * 32 + mt * 16 + 8 + (l >> 2)];
#pragma unroll
                for (int nt = 0; nt < 4; ++nt) {
                    SA[mt][nt][0] *= s0; SA[mt][nt][1] *= s0;
                    SA[mt][nt][2] *= s8; SA[mt][nt][3] *= s8;
                }
            }
        }
        __syncthreads();   // E: partials + staged(ch+1) + fDNr visible

        // ---- reduce phase ----
        {
            const int t = tid >> 5, j = l;
            float s = 0.0f;
#pragma unroll
            for (int ww = 0; ww < 16; ++ww) s += fPA[ww * 528 + t * 33 + j];
            fNA[t * 33 + j] = s;
        }
        if (tid < 256) {
            const int t = tid >> 4, tp = tid & 15;
            float p = 0.0f;
            if (tp <= t) {
#pragma unroll
                for (int ww = 0; ww < 16; ++ww) p += fPP[(t * 16 + tp) * 17 + ww];
            }
            const __nv_bfloat16 ph = __float2bfloat16(p);
            *(__nv_bfloat16*)(sm + OPH + t * 48 + tp * 2) = ph;
            *(__nv_bfloat16*)(sm + OPL + t * 48 + tp * 2) =
                __float2bfloat16(p - __bfloat162float(ph));
        } else {
            // den group sums for chunk ch+1 (staged this iteration)
            const int t = tid & 15, g = (tid >> 4) - 16;
            float s = 0.0f;
#pragma unroll
            for (int m = 0; m < 16; ++m) s += fDNr[(g * 16 + m) * 17 + t];
            fDP[((ch + 1) & 1) * 272 + t * 17 + g] = s;
        }
        __syncthreads();   // G

        // ---- output (warps 0-1) ----
        if (w < 2) {
            const int tt = l & 15;
            float dn = 0.0f;
#pragma unroll
            for (int g2 = 0; g2 < 16; ++g2) dn += fDP[buf * 272 + tt * 17 + g2];
            const float inv = 1.0f / (dn + kEPS);
            const float i0v = __shfl_sync(0xffffffffu, inv, l >> 2);
            const float i8v = __shfl_sync(0xffffffffu, inv, (l >> 2) + 8);

            u32 pa[4], pb[4], vvh[4], vvl[4];
            ldsm4(pa, sb + OPH + a48);
            ldsm4(pb, sb + OPL + a48);
            ldsm4(vvh, sbuf + SB_VH + a48 + w * 768);
            ldsm4(vvl, sbuf + SB_VL + a48 + w * 768);
            float o0[4] = {0, 0, 0, 0}, o1[4] = {0, 0, 0, 0};
            mma16816(o0, pa, vvh[0], vvh[2]);
            mma16816(o0, pb, vvh[0], vvh[2]);
            mma16816(o0, pa, vvl[0], vvl[2]);
            mma16816(o1, pa, vvh[1], vvh[3]);
            mma16816(o1, pb, vvh[1], vvh[3]);
            mma16816(o1, pa, vvl[1], vvl[3]);

#pragma unroll
            for (int h2 = 0; h2 < 2; ++h2) {
                const float* oo = h2 ? o1 : o0;
                const int cb = w * 16 + h2 * 8 + 2 * (l & 3);
#pragma unroll
                for (int e = 0; e < 4; ++e) {
                    const int tr = (l >> 2) + (e >> 1) * 8;
                    const int cc = cb + (e & 1);
                    const float val = (fNA[tr * 33 + cc] + oo[e]) *
                                      ((e >> 1) ? i8v : i0v);
                    gy[(size_t)(t0 + tr) * D_ + jbase + cc] = val;
                }
            }
        }
        __syncthreads();   // I: output reads done; staged[buf] reusable
    }
}

// -------------------- launch --------------------
extern "C" void kernel_launch(void* const* d_in, const int* in_sizes, int n_in,
                              void* d_out, int out_size)
{
    const float* x  = (const float*)d_in[0];
    const float* Wq = (const float*)d_in[1];
    const float* bq = (const float*)d_in[2];
    const float* Wk = (const float*)d_in[3];
    const float* bk = (const float*)d_in[4];
    const float* Wv = (const float*)d_in[5];
    const float* bv = (const float*)d_in[6];
    const float* Wa = (const float*)d_in[7];
    const float* ba = (const float*)d_in[8];
    float* y = (float*)d_out;

    static __nv_bfloat16 *p_xhi = nullptr, *p_xlo = nullptr;
    if (!p_xhi) {
        cudaGetSymbolAddress((void**)&p_xhi, g_xhi);
        cudaGetSymbolAddress((void**)&p_xlo, g_xlo);
    }

    convert_split_kernel<<<2048, 256>>>(x, p_xhi, p_xlo, (M_TOT * D_) / 2);
    dim3 wgrid(64, 4);
    convert_w_kernel<<<wgrid, 256>>>(Wq, Wk, Wv, Wa);

    cudaFuncSetAttribute(proj_mma_kernel,
                         cudaFuncAttributeMaxDynamicSharedMemorySize, GEMM_SMEM);
    dim3 ggrid(D_ / 128, M_TOT / 128, 4);
    proj_mma_kernel<<<ggrid, 256, GEMM_SMEM>>>(bq, bk, bv, ba);

    cudaFuncSetAttribute(scan_mma_kernel,
                         cudaFuncAttributeMaxDynamicSharedMemorySize, SCAN_SMEM);
    dim3 sgrid(D_ / 32, B_);
    scan_mma_kernel<<<sgrid, 512, SCAN_SMEM>>>(y);
}

// round 17
// speedup vs baseline: 1.0764x; 1.0764x over previous
#include <cuda_runtime.h>
#include <cuda_bf16.h>
#include <cstdint>
#include <cstddef>

#define B_ 8
#define S_ 4096
#define D_ 512
#define C_ 16
#define NCH_ (S_ / C_)
#define M_TOT (B_ * S_)

static __device__ __constant__ float kEPS = 1e-6f;

__device__ float g_q[(size_t)B_ * S_ * D_];
__device__ float g_k[(size_t)B_ * S_ * D_];
__device__ float g_v[(size_t)B_ * S_ * D_];
__device__ float g_a[(size_t)B_ * S_ * D_];
__device__ __nv_bfloat16 g_xhi[(size_t)M_TOT * D_];
__device__ __nv_bfloat16 g_xlo[(size_t)M_TOT * D_];
__device__ __nv_bfloat16 g_whi[4 * D_ * D_];
__device__ __nv_bfloat16 g_wlo[4 * D_ * D_];

typedef uint32_t u32;

__device__ __forceinline__ uint32_t smem_u32(const void* p) {
    uint32_t a;
    asm("{ .reg .u64 t; cvta.to.shared.u64 t, %1; cvt.u32.u64 %0, t; }"
        : "=r"(a) : "l"(p));
    return a;
}
__device__ __forceinline__ void ldsm4(u32* r, u32 addr) {
    asm volatile("ldmatrix.sync.aligned.m8n8.x4.shared.b16 {%0,%1,%2,%3}, [%4];"
                 : "=r"(r[0]), "=r"(r[1]), "=r"(r[2]), "=r"(r[3]) : "r"(addr));
}
__device__ __forceinline__ void ldsm4t(u32* r, u32 addr) {
    asm volatile("ldmatrix.sync.aligned.m8n8.x4.trans.shared.b16 {%0,%1,%2,%3}, [%4];"
                 : "=r"(r[0]), "=r"(r[1]), "=r"(r[2]), "=r"(r[3]) : "r"(addr));
}
__device__ __forceinline__ u32 movmt(u32 a) {
    u32 d;
    asm volatile("movmatrix.sync.aligned.m8n8.trans.b16 %0, %1;" : "=r"(d) : "r"(a));
    return d;
}
__device__ __forceinline__ u32 bfpack(float lo, float hi) {
    u32 d;
    asm("cvt.rn.bf16x2.f32 %0, %1, %2;" : "=r"(d) : "f"(hi), "f"(lo));
    return d;
}
__device__ __forceinline__ float bfres(float x) {
    return x - __bfloat162float(__float2bfloat16(x));
}
__device__ __forceinline__ void mma16816(float* c, const u32* a, u32 b0, u32 b1) {
    asm volatile(
        "mma.sync.aligned.m16n8k16.row.col.f32.bf16.bf16.f32 "
        "{%0,%1,%2,%3}, {%4,%5,%6,%7}, {%8,%9}, {%0,%1,%2,%3};"
        : "+f"(c[0]), "+f"(c[1]), "+f"(c[2]), "+f"(c[3])
        : "r"(a[0]), "r"(a[1]), "r"(a[2]), "r"(a[3]), "r"(b0), "r"(b1));
}
__device__ __forceinline__ void cp16(u32 saddr, const void* g) {
    asm volatile("cp.async.cg.shared.global [%0], [%1], 16;" :: "r"(saddr), "l"(g));
}
__device__ __forceinline__ float act_apply(float x, int act) {
    if (act == 1) return fmaxf(x, 0.0f);
    if (act == 2) return 1.0f / (1.0f + __expf(-x));
    return x;
}

// -------------------- converts --------------------
__global__ void __launch_bounds__(256) convert_split_kernel(
    const float* __restrict__ src, __nv_bfloat16* __restrict__ hi,
    __nv_bfloat16* __restrict__ lo, int n2)
{
    const int idx = blockIdx.x * blockDim.x + threadIdx.x;
    const int stride = gridDim.x * blockDim.x;
    const float2* s2 = (const float2*)src;
    __nv_bfloat162* h2 = (__nv_bfloat162*)hi;
    __nv_bfloat162* l2 = (__nv_bfloat162*)lo;
    for (int i = idx; i < n2; i += stride) {
        const float2 x = s2[i];
        const __nv_bfloat16 h0 = __float2bfloat16(x.x);
        const __nv_bfloat16 h1 = __float2bfloat16(x.y);
        __nv_bfloat162 hh; hh.x = h0; hh.y = h1;
        __nv_bfloat162 ll;
        ll.x = __float2bfloat16(x.x - __bfloat162float(h0));
        ll.y = __float2bfloat16(x.y - __bfloat162float(h1));
        h2[i] = hh; l2[i] = ll;
    }
}

__global__ void __launch_bounds__(256) convert_w_kernel(
    const float* __restrict__ w0, const float* __restrict__ w1,
    const float* __restrict__ w2, const float* __restrict__ w3)
{
    const int wsel = blockIdx.y;
    const float* src = (wsel == 0) ? w0 : (wsel == 1) ? w1 : (wsel == 2) ? w2 : w3;
    __nv_bfloat162* h2 = (__nv_bfloat162*)(g_whi + (size_t)wsel * D_ * D_);
    __nv_bfloat162* l2 = (__nv_bfloat162*)(g_wlo + (size_t)wsel * D_ * D_);
    const float2* s2 = (const float2*)src;
    const int n2 = (D_ * D_) / 2;
    const int idx = blockIdx.x * blockDim.x + threadIdx.x;
    const int stride = gridDim.x * blockDim.x;
    for (int i = idx; i < n2; i += stride) {
        const float2 x = s2[i];
        const __nv_bfloat16 h0 = __float2bfloat16(x.x);
        const __nv_bfloat16 h1 = __float2bfloat16(x.y);
        __nv_bfloat162 hh; hh.x = h0; hh.y = h1;
        __nv_bfloat162 ll;
        ll.x = __float2bfloat16(x.x - __bfloat162float(h0));
        ll.y = __float2bfloat16(x.y - __bfloat162float(h1));
        h2[i] = hh; l2[i] = ll;
    }
}

// -------------------- projection GEMM (proven) --------------------
#define GK 32
#define NKCH (D_ / GK)
#define ROWB 80
#define TILEB (128 * ROWB)
#define ABUF_HI 0
#define ABUF_LO TILEB
#define BBUF_HI (2 * TILEB)
#define BBUF_LO (3 * TILEB)
#define BUFB (4 * TILEB)
#define GEMM_SMEM (2 * BUFB)

__global__ void __launch_bounds__(256, 1) proj_mma_kernel(
    const float* __restrict__ bq, const float* __restrict__ bk,
    const float* __restrict__ bv, const float* __restrict__ ba)
{
    extern __shared__ __align__(16) char smem[];
    const u32 sbase = smem_u32(smem);
    const int pz = blockIdx.z;
    const float* bias; float* out; int act;
    if (pz == 0)      { bias = bq; out = g_q; act = 1; }
    else if (pz == 1) { bias = bk; out = g_k; act = 1; }
    else if (pz == 2) { bias = bv; out = g_v; act = 0; }
    else              { bias = ba; out = g_a; act = 2; }

    const int tid = threadIdx.x, w = tid >> 5, l = tid & 31;
    const int wm = w >> 2, wn = w & 3;
    const int mBase = blockIdx.y * 128, nBase = blockIdx.x * 128;
    const __nv_bfloat16* Whi = g_whi + (size_t)pz * D_ * D_;
    const __nv_bfloat16* Wlo = g_wlo + (size_t)pz * D_ * D_;
    const int r0s = tid >> 2, s0s = tid & 3;
    const int r1s = (tid + 256) >> 2, s1s = tid & 3;

    auto load_chunk = [&](int buf, int kc) {
        const u32 sb = sbase + buf * BUFB;
        const int k0 = kc * GK;
        {
            const size_t ga = (size_t)(mBase + r0s) * D_ + k0 + s0s * 8;
            const size_t gb = (size_t)(nBase + r0s) * D_ + k0 + s0s * 8;
            const u32 so = r0s * ROWB + s0s * 16;
            cp16(sb + ABUF_HI + so, g_xhi + ga);
            cp16(sb + ABUF_LO + so, g_xlo + ga);
            cp16(sb + BBUF_HI + so, Whi + gb);
            cp16(sb + BBUF_LO + so, Wlo + gb);
        }
        {
            const size_t ga = (size_t)(mBase + r1s) * D_ + k0 + s1s * 8;
            const size_t gb = (size_t)(nBase + r1s) * D_ + k0 + s1s * 8;
            const u32 so = r1s * ROWB + s1s * 16;
            cp16(sb + ABUF_HI + so, g_xhi + ga);
            cp16(sb + ABUF_LO + so, g_xlo + ga);
            cp16(sb + BBUF_HI + so, Whi + gb);
            cp16(sb + BBUF_LO + so, Wlo + gb);
        }
        asm volatile("cp.async.commit_group;");
    };

    float acc[4][4][4];
#pragma unroll
    for (int i = 0; i < 4; ++i)
#pragma unroll
        for (int j = 0; j < 4; ++j)
#pragma unroll
            for (int e = 0; e < 4; ++e) acc[i][j][e] = 0.0f;

    const int lrow = l & 15, lcol16 = (l >> 4) & 1;
    load_chunk(0, 0);

#pragma unroll 1
    for (int kc = 0; kc < NKCH; ++kc) {
        const int buf = kc & 1;
        if (kc + 1 < NKCH) {
            load_chunk(buf ^ 1, kc + 1);
            asm volatile("cp.async.wait_group 1;");
        } else {
            asm volatile("cp.async.wait_group 0;");
        }
        __syncthreads();
        const u32 sb = sbase + buf * BUFB;
#pragma unroll
        for (int kh = 0; kh < 2; ++kh) {
            const u32 coff = kh * 32 + lcol16 * 16;
            u32 ah[4][4], al[4][4];
#pragma unroll
            for (int mt = 0; mt < 4; ++mt) {
                const u32 ra = (wm * 64 + mt * 16 + lrow) * ROWB + coff;
                ldsm4(ah[mt], sb + ABUF_HI + ra);
                ldsm4(al[mt], sb + ABUF_LO + ra);
            }
            u32 bh[2][4], bl[2][4];
#pragma unroll
            for (int bt = 0; bt < 2; ++bt) {
                const u32 rb = (wn * 32 + bt * 16 + lrow) * ROWB + coff;
                ldsm4(bh[bt], sb + BBUF_HI + rb);
                ldsm4(bl[bt], sb + BBUF_LO + rb);
            }
#pragma unroll
            for (int mt = 0; mt < 4; ++mt)
#pragma unroll
                for (int nt = 0; nt < 4; ++nt) {
                    const int bt = nt >> 1, hf = nt & 1;
                    mma16816(acc[mt][nt], ah[mt], bh[bt][hf], bh[bt][hf + 2]);
                    mma16816(acc[mt][nt], ah[mt], bl[bt][hf], bl[bt][hf + 2]);
                    mma16816(acc[mt][nt], al[mt], bh[bt][hf], bh[bt][hf + 2]);
                }
        }
        __syncthreads();
    }

#pragma unroll
    for (int nt = 0; nt < 4; ++nt) {
        const int col = nBase + wn * 32 + nt * 8 + 2 * (l & 3);
        const float2 b2 = *(const float2*)(bias + col);
#pragma unroll
        for (int mt = 0; mt < 4; ++mt) {
            const int row = mBase + wm * 64 + mt * 16 + (l >> 2);
            float2 r0, r1;
            r0.x = act_apply(acc[mt][nt][0] + b2.x, act);
            r0.y = act_apply(acc[mt][nt][1] + b2.y, act);
            r1.x = act_apply(acc[mt][nt][2] + b2.x, act);
            r1.y = act_apply(acc[mt][nt][3] + b2.y, act);
            *(float2*)(out + (size_t)row * D_ + col) = r0;
            *(float2*)(out + (size_t)(row + 8) * D_ + col) = r1;
        }
    }
}

// -------------------- tensor-core chunked scan (r12 base) --------------------
// Changes vs r12: (1) raw f32 V + raw f32 reduced-P staged; output phase is
// SIMT f32 P.V across ALL 512 threads (was 2-warp mma). (2) L2 prefetch of
// chunk ch+1 issued at the top of the mma phase.
#define ST_I 1040
#define OQH 0
#define OQL (OQH + 16*ST_I)
#define OKH (OQL + 16*ST_I)
#define OKL (OKH + 16*ST_I)
#define OVH (OKL + 16*ST_I)
#define OVL (OVH + 32*48)
#define OVR (OVL + 32*48)              // raw V f32 [16 t][33]
#define OPT (OVR + 16*33*4)            // reduced P f32 [16 t][17]
#define OAC (OPT + 16*17*4)
#define OPP (OAC + 2048)
#define OPA (OPP + 256*17*4)
#define ONA (OPA + 16*528*4)
#define ODN (ONA + 528*4)
#define ODP (ODN + 512*17*4)           // [16 t][33] group sums (32 groups)
#define SCAN_SMEM (ODP + 16*33*4)

__global__ void __launch_bounds__(512, 1) scan_mma_kernel(float* __restrict__ y)
{
    extern __shared__ __align__(16) char sm[];
    const u32 sb = smem_u32(sm);
    float* fAC = (float*)(sm + OAC);
    float* fPP = (float*)(sm + OPP);
    float* fPA = (float*)(sm + OPA);
    float* fNA = (float*)(sm + ONA);
    float* fDN = (float*)(sm + ODN);
    float* fDP = (float*)(sm + ODP);
    float* fVR = (float*)(sm + OVR);
    float* fPT = (float*)(sm + OPT);

    const int b = blockIdx.y, jbase = blockIdx.x * 32;
    const int tid = threadIdx.x, w = tid >> 5, l = tid & 31;
    const float* gq = g_q + (size_t)b * S_ * D_;
    const float* gk = g_k + (size_t)b * S_ * D_;
    const float* gv = g_v + (size_t)b * S_ * D_;
    const float* ga = g_a + (size_t)b * S_ * D_;
    float* gy = y + (size_t)b * S_ * D_;

    float SA[2][4][4];
#pragma unroll
    for (int mt = 0; mt < 2; ++mt)
#pragma unroll
        for (int nt = 0; nt < 4; ++nt)
#pragma unroll
            for (int e = 0; e < 4; ++e) SA[mt][nt][e] = 0.0f;
    float zreg = 0.0f;

    const int l7 = l & 7;
    const u32 aTI  = (u32)((l7 + 8 * ((l >> 3) & 1)) * ST_I + 16 * (l >> 4));
    const u32 aTIt = (u32)((l7 + 8 * ((l >> 4) & 1)) * ST_I + 16 * ((l >> 3) & 1));
    const u32 a48  = (u32)((l7 + 8 * ((l >> 3) & 1)) * 48 + 16 * (l >> 4));

    // warm L2 for chunk 0
    {
        const int tpf = l & 15;
        const size_t roff = (size_t)tpf * D_ + w * 32;
        if (l < 16) {
            asm volatile("prefetch.global.L2 [%0];" :: "l"(gq + roff));
            asm volatile("prefetch.global.L2 [%0];" :: "l"(ga + roff));
        } else {
            asm volatile("prefetch.global.L2 [%0];" :: "l"(gk + roff));
            if (w == 0)
                asm volatile("prefetch.global.L2 [%0];"
                             :: "l"(gv + (size_t)tpf * D_ + jbase));
        }
    }

#pragma unroll 1
    for (int ch = 0; ch < NCH_; ++ch) {
        const int t0 = ch * C_;
        __syncthreads();   // B0

        // ---- stage: decay prep, z/den, bf16 staging into [t][i] ----
        {
            const int i_ = tid;
            float av[16], A[16], iA[16], qv[16], kv[16];
#pragma unroll
            for (int t = 0; t < 16; ++t) av[t] = ga[(size_t)(t0 + t) * D_ + i_];
#pragma unroll
            for (int t = 0; t < 16; ++t) qv[t] = gq[(size_t)(t0 + t) * D_ + i_];
#pragma unroll
            for (int t = 0; t < 16; ++t) kv[t] = gk[(size_t)(t0 + t) * D_ + i_];
            A[0] = av[0];
#pragma unroll
            for (int t = 1; t < 16; ++t) A[t] = A[t - 1] * av[t];
            iA[15] = __frcp_rn(A[15]);
#pragma unroll
            for (int t = 15; t >= 1; --t) iA[t - 1] = iA[t] * av[t];
            float zu = zreg;
#pragma unroll
            for (int t = 0; t < 16; ++t) {
                const float qt = qv[t] * A[t];
                const float kt = kv[t] * iA[t];
                zu += kt;
                fDN[i_ * 17 + t] = qt * zu;
                const __nv_bfloat16 qh = __float2bfloat16(qt);
                const __nv_bfloat16 kh = __float2bfloat16(kt);
                *(__nv_bfloat16*)(sm + OQH + t * ST_I + i_ * 2) = qh;
                *(__nv_bfloat16*)(sm + OQL + t * ST_I + i_ * 2) =
                    __float2bfloat16(qt - __bfloat162float(qh));
                *(__nv_bfloat16*)(sm + OKH + t * ST_I + i_ * 2) = kh;
                *(__nv_bfloat16*)(sm + OKL + t * ST_I + i_ * 2) =
                    __float2bfloat16(kt - __bfloat162float(kh));
            }
            zreg = A[15] * zu;
            fAC[i_] = A[15];
        }
        // V staging [j][t] bf16 + raw f32 [t][j]
        {
            const int t = tid >> 5, j = l;
            const float vv = gv[(size_t)(t0 + t) * D_ + jbase + j];
            const __nv_bfloat16 vh = __float2bfloat16(vv);
            *(__nv_bfloat16*)(sm + OVH + j * 48 + t * 2) = vh;
            *(__nv_bfloat16*)(sm + OVL + j * 48 + t * 2) =
                __float2bfloat16(vv - __bfloat162float(vh));
            fVR[t * 33 + j] = vv;
        }
        __syncthreads();   // B1

        // ---- L2 prefetch for chunk+1 (hidden under mma) ----
        if (ch + 1 < NCH_) {
            const int tpf = l & 15;
            const size_t roff = (size_t)(t0 + 16 + tpf) * D_ + w * 32;
            if (l < 16) {
                asm volatile("prefetch.global.L2 [%0];" :: "l"(gq + roff));
                asm volatile("prefetch.global.L2 [%0];" :: "l"(ga + roff));
            } else {
                asm volatile("prefetch.global.L2 [%0];" :: "l"(gk + roff));
                if (w == 0)
                    asm volatile("prefetch.global.L2 [%0];"
                                 :: "l"(gv + (size_t)(t0 + 16 + tpf) * D_ + jbase));
            }
        }

        // ---- mma phase ----
        u32 qhf[2][4], qlf[2][4];
        {
            u32 khf[2][4], klf[2][4];
#pragma unroll
            for (int ks = 0; ks < 2; ++ks) {
                const u32 io = (u32)(w * 32 + ks * 16) * 2;
                ldsm4(qhf[ks], sb + OQH + aTI + io);
                ldsm4(qlf[ks], sb + OQL + aTI + io);
                ldsm4(khf[ks], sb + OKH + aTI + io);
                ldsm4(klf[ks], sb + OKL + aTI + io);
            }
            float p0[4] = {0, 0, 0, 0}, p1[4] = {0, 0, 0, 0};
#pragma unroll
            for (int ks = 0; ks < 2; ++ks) {
                mma16816(p0, qhf[ks], khf[ks][0], khf[ks][2]);
                mma16816(p0, qlf[ks], khf[ks][0], khf[ks][2]);
                mma16816(p0, qhf[ks], klf[ks][0], klf[ks][2]);
                mma16816(p1, qhf[ks], khf[ks][1], khf[ks][3]);
                mma16816(p1, qlf[ks], khf[ks][1], khf[ks][3]);
                mma16816(p1, qhf[ks], klf[ks][1], klf[ks][3]);
            }
#pragma unroll
            for (int e = 0; e < 4; ++e) {
                const int tr = (l >> 2) + (e >> 1) * 8;
                const int tc = 2 * (l & 3) + (e & 1);
                fPP[(tr * 16 + tc) * 17 + w] = p0[e];
                fPP[(tr * 16 + tc + 8) * 17 + w] = p1[e];
            }
        }
        {
            float qs[4][4];
#pragma unroll
            for (int nt = 0; nt < 4; ++nt)
#pragma unroll
                for (int e = 0; e < 4; ++e) qs[nt][e] = 0.0f;
#pragma unroll
            for (int mt = 0; mt < 2; ++mt)
#pragma unroll
                for (int nt = 0; nt < 4; ++nt) {
                    const float c0 = SA[mt][nt][0], c1 = SA[mt][nt][1];
                    const float c2 = SA[mt][nt][2], c3 = SA[mt][nt][3];
                    const u32 b0h = movmt(bfpack(c0, c1));
                    const u32 b1h = movmt(bfpack(c2, c3));
                    const u32 b0l = movmt(bfpack(bfres(c0), bfres(c1)));
                    const u32 b1l = movmt(bfpack(bfres(c2), bfres(c3)));
                    mma16816(qs[nt], qhf[mt], b0h, b1h);
                    mma16816(qs[nt], qlf[mt], b0h, b1h);
                    mma16816(qs[nt], qhf[mt], b0l, b1l);
                }
#pragma unroll
            for (int nt = 0; nt < 4; ++nt)
#pragma unroll
                for (int e = 0; e < 4; ++e) {
                    const int tr = (l >> 2) + (e >> 1) * 8;
                    const int j = nt * 8 + 2 * (l & 3) + (e & 1);
                    fPA[w * 528 + tr * 33 + j] = qs[nt][e];
                }
        }
        {
            u32 ah[2][4], al[2][4], vh[2][4], vl[2][4];
#pragma unroll
            for (int mt = 0; mt < 2; ++mt) {
                const u32 io = (u32)(w * 32 + mt * 16) * 2;
                ldsm4t(ah[mt], sb + OKH + aTIt + io);
                ldsm4t(al[mt], sb + OKL + aTIt + io);
            }
#pragma unroll
            for (int jg = 0; jg < 2; ++jg) {
                ldsm4(vh[jg], sb + OVH + a48 + jg * 768);
                ldsm4(vl[jg], sb + OVL + a48 + jg * 768);
            }
#pragma unroll
            for (int mt = 0; mt < 2; ++mt)
#pragma unroll
                for (int nt = 0; nt < 4; ++nt) {
                    const int jg = nt >> 1, hf = nt & 1;
                    mma16816(SA[mt][nt], ah[mt], vh[jg][hf], vh[jg][hf + 2]);
                    mma16816(SA[mt][nt], al[mt], vh[jg][hf], vh[jg][hf + 2]);
                    mma16816(SA[mt][nt], ah[mt], vl[jg][hf], vl[jg][hf + 2]);
                }
#pragma unroll
            for (int mt = 0; mt < 2; ++mt) {
                const float s0 = fAC[w * 32 + mt * 16 + (l >> 2)];
                const float s8 = fAC[w * 32 + mt * 16 + 8 + (l >> 2)];
#pragma unroll
                for (int nt = 0; nt < 4; ++nt) {
                    SA[mt][nt][0] *= s0; SA[mt][nt][1] *= s0;
                    SA[mt][nt][2] *= s8; SA[mt][nt][3] *= s8;
                }
            }
        }
        __syncthreads();   // B2

        // ---- reduce phase ----
        {
            const int t = tid >> 5, j = l;
            float s = 0.0f;
#pragma unroll
            for (int ww = 0; ww < 16; ++ww) s += fPA[ww * 528 + t * 33 + j];
            fNA[t * 33 + j] = s;
        }
        if (tid < 256) {
            const int t = tid >> 4, tp = tid & 15;
            float p = 0.0f;
            if (tp <= t) {
#pragma unroll
                for (int ww = 0; ww < 16; ++ww) p += fPP[(t * 16 + tp) * 17 + ww];
            }
            fPT[t * 17 + tp] = p;   // f32 (was bf16 hi/lo)
        }
        {
            const int t = tid & 15, g = tid >> 4;
            float s = 0.0f;
#pragma unroll
            for (int m = 0; m < 16; ++m) s += fDN[(g * 16 + m) * 17 + t];
            fDP[t * 33 + g] = s;
        }
        __syncthreads();   // B3

        // ---- output: ALL 512 threads, SIMT f32 P.V ----
        {
            const int t = tid >> 5, j = l;
            // denominator: lane g loads group sum, warp butterfly
            float dn = fDP[t * 33 + l];
#pragma unroll
            for (int off = 16; off; off >>= 1)
                dn += __shfl_xor_sync(0xffffffffu, dn, off);
            const float inv = 1.0f / (dn + kEPS);

            float acc = fNA[t * 33 + j];
            const float* pRow = fPT + t * 17;
            const float* vCol = fVR + j;
#pragma unroll
            for (int tp = 0; tp < 16; ++tp)
                acc += pRow[tp] * vCol[tp * 33];
            gy[(size_t)(t0 + t) * D_ + jbase + j] = acc * inv;
        }
    }
}

// -------------------- launch --------------------
extern "C" void kernel_launch(void* const* d_in, const int* in_sizes, int n_in,
                              void* d_out, int out_size)
{
    const float* x  = (const float*)d_in[0];
    const float* Wq = (const float*)d_in[1];
    const float* bq = (const float*)d_in[2];
    const float* Wk = (const float*)d_in[3];
    const float* bk = (const float*)d_in[4];
    const float* Wv = (const float*)d_in[5];
    const float* bv = (const float*)d_in[6];
    const float* Wa = (const float*)d_in[7];
    const float* ba = (const float*)d_in[8];
    float* y = (float*)d_out;

    static __nv_bfloat16 *p_xhi = nullptr, *p_xlo = nullptr;
    if (!p_xhi) {
        cudaGetSymbolAddress((void**)&p_xhi, g_xhi);
        cudaGetSymbolAddress((void**)&p_xlo, g_xlo);
    }

    convert_split_kernel<<<2048, 256>>>(x, p_xhi, p_xlo, (M_TOT * D_) / 2);
    dim3 wgrid(64, 4);
    convert_w_kernel<<<wgrid, 256>>>(Wq, Wk, Wv, Wa);

    cudaFuncSetAttribute(proj_mma_kernel,
                         cudaFuncAttributeMaxDynamicSharedMemorySize, GEMM_SMEM);
    dim3 ggrid(D_ / 128, M_TOT / 128, 4);
    proj_mma_kernel<<<ggrid, 256, GEMM_SMEM>>>(bq, bk, bv, ba);

    cudaFuncSetAttribute(scan_mma_kernel,
                         cudaFuncAttributeMaxDynamicSharedMemorySize, SCAN_SMEM);
    dim3 sgrid(D_ / 32, B_);
    scan_mma_kernel<<<sgrid, 512, SCAN_SMEM>>>(y);
}